// round 9
// baseline (speedup 1.0000x reference)
#include <cuda_runtime.h>
#include <cuda_fp16.h>
#include <cstdint>
#include <cstddef>

// ---------------- problem constants ----------------
static constexpr int BH  = 8;     // B*H = 2*4
static constexpr int T   = 2048;  // sequence
static constexpr int HD  = 4096;  // head feature dim N
static constexpr unsigned long long QR_ELEMS = (unsigned long long)BH * T * HD; // 67,108,864
static constexpr unsigned long long S_ELEMS  = (unsigned long long)BH * T * T;  // 33,554,432

// scratch (allocation-free rule: __device__ globals)
__device__ __half g_QR[QR_ELEMS];   // rope(Q), fp16, [bh][t][n]
__device__ __half g_Vt[QR_ELEMS];   // V transposed, fp16, [bh][n][s]
__device__ __half g_S [S_ELEMS];    // scaled scores, fp16, [bh][t][s]

#define DINLINE __device__ __forceinline__

// ---------------- PTX helpers (sm_103 BASE target only — no "a" features) ----
DINLINE uint32_t smem_u32(const void* p) {
    uint32_t a;
    asm("{ .reg .u64 t; cvta.to.shared.u64 t, %1; cvt.u32.u64 %0, t; }" : "=r"(a) : "l"(p));
    return a;
}

#define SWZ128(o) ((o) ^ (((o) >> 3) & 0x70))

DINLINE void cp_async16(uint32_t dst, const void* src) {
    asm volatile("cp.async.cg.shared.global [%0], [%1], 16;" :: "r"(dst), "l"(src) : "memory");
}
#define CP_COMMIT() asm volatile("cp.async.commit_group;" ::: "memory")
#define CP_WAIT(n)  asm volatile("cp.async.wait_group %0;" :: "n"(n) : "memory")

DINLINE void ldsm_x4(uint32_t* r, uint32_t addr) {
    asm volatile("ldmatrix.sync.aligned.m8n8.x4.shared.b16 {%0,%1,%2,%3}, [%4];"
        : "=r"(r[0]), "=r"(r[1]), "=r"(r[2]), "=r"(r[3]) : "r"(addr));
}
DINLINE void ldsm_x2(uint32_t* r, uint32_t addr) {
    asm volatile("ldmatrix.sync.aligned.m8n8.x2.shared.b16 {%0,%1}, [%2];"
        : "=r"(r[0]), "=r"(r[1]) : "r"(addr));
}

DINLINE void mma16816(float* c, const uint32_t* a, const uint32_t* b) {
    asm volatile(
        "mma.sync.aligned.m16n8k16.row.col.f32.f16.f16.f32 "
        "{%0,%1,%2,%3}, {%4,%5,%6,%7}, {%8,%9}, {%0,%1,%2,%3};"
        : "+f"(c[0]), "+f"(c[1]), "+f"(c[2]), "+f"(c[3])
        : "r"(a[0]), "r"(a[1]), "r"(a[2]), "r"(a[3]), "r"(b[0]), "r"(b[1]));
}

// ---------------- prep kernels ----------------

// QR = rope(Q) in fp16. One thread per (even,odd) pair.
__global__ void rope_kernel(const float* __restrict__ Q, __half* __restrict__ qr) {
    long long p = (long long)blockIdx.x * blockDim.x + threadIdx.x; // pair index
    int n2 = (int)(p & (HD / 2 - 1));        // pair index within row
    long long rest = p >> 11;                // / 2048
    int t = (int)(rest & (T - 1));
    float n = (float)(2 * n2);
    // freq = 2^(-n/256) / (2*pi)
    float freq = exp2f(n * (-1.0f / 256.0f)) * 0.15915494309189535f;
    float phase = (float)t * freq;
    float frac = phase - floorf(phase);
    float ph = frac * 6.283185307179586f;
    float s, c;
    sincosf(ph, &s, &c);
    float2 q = ((const float2*)Q)[p];
    __half2 h = __floats2half2_rn(q.x * c - q.y * s, q.y * c + q.x * s);
    ((__half2*)qr)[p] = h;
}

// Vt[bh][n][s] = (half)V[bh][s][n]
__global__ void vtrans_kernel(const float* __restrict__ V, __half* __restrict__ vt) {
    __shared__ __half tile[32][33];
    int bh = blockIdx.z;
    int s0 = blockIdx.x * 32;
    int n0 = blockIdx.y * 32;
    int tx = threadIdx.x, ty = threadIdx.y;
    const float* vsrc = V + (size_t)bh * T * HD;
    #pragma unroll
    for (int j = 0; j < 32; j += 8)
        tile[ty + j][tx] = __float2half(vsrc[(size_t)(s0 + ty + j) * HD + n0 + tx]);
    __syncthreads();
    __half* vdst = vt + (size_t)bh * HD * T;
    #pragma unroll
    for (int j = 0; j < 32; j += 8)
        vdst[(size_t)(n0 + ty + j) * T + s0 + tx] = tile[tx][ty + j];
}

// ---------------- multistage HMMA GEMM: C[m,n] = sum_k A[m,k]*B[n,k] --------
// A: [Mtot, K] fp16 K-major.  B: [Ntot, K] fp16 K-major.  Per-bh slab via blockIdx.z.

static constexpr int TILE_M = 128;
static constexpr int TILE_N = 256;
static constexpr int KCH    = 64;               // halves per chunk = 128 B row (SW128 atom)
static constexpr int STAGES = 4;
static constexpr int THREADS = 512;             // 16 warps, 4x4 warp grid
static constexpr int A_STAGE_BYTES = TILE_M * 128;   // 16 KB
static constexpr int B_STAGE_BYTES = TILE_N * 128;   // 32 KB
static constexpr int OFF_A = 0;
static constexpr int OFF_B = STAGES * A_STAGE_BYTES;             // 65536
static constexpr int SMEM_BYTES = OFF_B + STAGES * B_STAGE_BYTES; // 196608 (192 KB)

template <bool HALF_OUT>
__global__ void __launch_bounds__(THREADS, 1)
gemm_kernel(const __half* __restrict__ A, const __half* __restrict__ B,
            void* __restrict__ C, int K, int ldc, float scale)
{
    extern __shared__ char smem[];
    uint32_t sb = smem_u32(smem);
    const int tid  = threadIdx.x;
    const int lane = tid & 31;
    const int w    = tid >> 5;
    const int warp_m = w & 3;        // 4 x 32 rows
    const int warp_n = w >> 2;       // 4 x 64 cols
    const int bh = blockIdx.z;
    const int m0 = blockIdx.y * TILE_M;
    const int n0 = blockIdx.x * TILE_N;
    const int NC = K / KCH;
    const size_t Mtot = (size_t)gridDim.y * TILE_M;
    const size_t Ntot = (size_t)gridDim.x * TILE_N;

    const __half* Abase = A + ((size_t)bh * Mtot + m0) * K;
    const __half* Bbase = B + ((size_t)bh * Ntot + n0) * K;

    // producer: load chunk kc into stage slot
    auto issue_chunk = [&](int kc) {
        int slot = kc & (STAGES - 1);
        const __half* asrc = Abase + kc * KCH;
        uint32_t as = sb + OFF_A + slot * A_STAGE_BYTES;
        #pragma unroll
        for (int j = 0; j < 2; j++) {            // A: 128 rows * 8 chunks / 512 thr
            int i = tid + j * THREADS;
            int r = i >> 3, c8 = i & 7;
            cp_async16(as + SWZ128(r * 128 + c8 * 16), asrc + (size_t)r * K + c8 * 8);
        }
        const __half* bsrc = Bbase + kc * KCH;
        uint32_t bs = sb + OFF_B + slot * B_STAGE_BYTES;
        #pragma unroll
        for (int j = 0; j < 4; j++) {            // B: 256 rows * 8 chunks / 512 thr
            int i = tid + j * THREADS;
            int r = i >> 3, c8 = i & 7;
            cp_async16(bs + SWZ128(r * 128 + c8 * 16), bsrc + (size_t)r * K + c8 * 8);
        }
    };

    // prologue: chunks 0..STAGES-2
    #pragma unroll
    for (int s = 0; s < STAGES - 1; s++) { issue_chunk(s); CP_COMMIT(); }

    float acc[2][8][4];
    #pragma unroll
    for (int mt = 0; mt < 2; mt++)
        #pragma unroll
        for (int nt = 0; nt < 8; nt++)
            #pragma unroll
            for (int j = 0; j < 4; j++) acc[mt][nt][j] = 0.0f;

    // precomputed ldmatrix lane geometry
    const int a_row = warp_m * 32 + (lane & 15);         // + mt*16
    const int a_chk = lane >> 4;                         // + 2*ks
    const int b_row = warp_n * 64 + (lane & 7);          // + nt*8
    const int b_chk = (lane >> 3) & 1;                   // + 2*ks

    for (int kc = 0; kc < NC; kc++) {
        CP_WAIT(STAGES - 2);
        __syncthreads();
        // refill the slot freed last iteration (slot (kc-1)%S == (kc+3)%S)
        if (kc + STAGES - 1 < NC) issue_chunk(kc + STAGES - 1);
        CP_COMMIT();

        int slot = kc & (STAGES - 1);
        uint32_t as = sb + OFF_A + slot * A_STAGE_BYTES;
        uint32_t bs = sb + OFF_B + slot * B_STAGE_BYTES;

        #pragma unroll
        for (int ks = 0; ks < 4; ks++) {
            uint32_t afrag[2][4];
            #pragma unroll
            for (int mt = 0; mt < 2; mt++) {
                int row = a_row + mt * 16;
                int chk = 2 * ks + a_chk;
                ldsm_x4(afrag[mt], as + row * 128 + (((chk ^ (row & 7))) << 4));
            }
            uint32_t bfrag[8][2];
            #pragma unroll
            for (int nt = 0; nt < 8; nt++) {
                int row = b_row + nt * 8;
                int chk = 2 * ks + b_chk;
                ldsm_x2(bfrag[nt], bs + row * 128 + (((chk ^ (row & 7))) << 4));
            }
            #pragma unroll
            for (int mt = 0; mt < 2; mt++)
                #pragma unroll
                for (int nt = 0; nt < 8; nt++)
                    mma16816(acc[mt][nt], afrag[mt], bfrag[nt]);
        }
    }
    CP_WAIT(0);

    // -------- epilogue --------
    const int group = lane >> 2, tq = lane & 3;
    #pragma unroll
    for (int mt = 0; mt < 2; mt++) {
        #pragma unroll
        for (int g2 = 0; g2 < 2; g2++) {
            int row = m0 + warp_m * 32 + mt * 16 + group + g2 * 8;
            size_t rbase = ((size_t)bh * Mtot + row) * ldc + n0 + warp_n * 64 + tq * 2;
            if (HALF_OUT) {
                __half* outp = (__half*)C + rbase;
                #pragma unroll
                for (int nt = 0; nt < 8; nt++) {
                    __half2 h = __floats2half2_rn(acc[mt][nt][g2 * 2 + 0] * scale,
                                                  acc[mt][nt][g2 * 2 + 1] * scale);
                    *reinterpret_cast<__half2*>(outp + nt * 8) = h;
                }
            } else {
                float* outp = (float*)C + rbase;
                #pragma unroll
                for (int nt = 0; nt < 8; nt++) {
                    float2 v = make_float2(acc[mt][nt][g2 * 2 + 0] * scale,
                                           acc[mt][nt][g2 * 2 + 1] * scale);
                    *reinterpret_cast<float2*>(outp + nt * 8) = v;
                }
            }
        }
    }
}

// ---------------- launch ----------------
extern "C" void kernel_launch(void* const* d_in, const int* in_sizes, int n_in,
                              void* d_out, int out_size)
{
    (void)in_sizes; (void)n_in; (void)out_size;
    const float* Q = (const float*)d_in[0];
    // d_in[1] (K) is unused by the reference computation
    const float* V = (const float*)d_in[2];

    void *qr_p = nullptr, *vt_p = nullptr, *s_p = nullptr;
    cudaGetSymbolAddress(&qr_p, g_QR);
    cudaGetSymbolAddress(&vt_p, g_Vt);
    cudaGetSymbolAddress(&s_p,  g_S);
    __half* QR = (__half*)qr_p;
    __half* Vt = (__half*)vt_p;
    __half* S  = (__half*)s_p;

    cudaFuncSetAttribute((const void*)gemm_kernel<true>,
                         cudaFuncAttributeMaxDynamicSharedMemorySize, SMEM_BYTES);
    cudaFuncSetAttribute((const void*)gemm_kernel<false>,
                         cudaFuncAttributeMaxDynamicSharedMemorySize, SMEM_BYTES);

    // 1) rope(Q) -> QR fp16
    rope_kernel<<<(unsigned)(QR_ELEMS / 2 / 256), 256>>>(Q, QR);

    // 2) V -> Vt fp16 (transpose)
    vtrans_kernel<<<dim3(T / 32, HD / 32, BH), dim3(32, 8)>>>(V, Vt);

    // 3) S = (QR * QR^T) * (1/64), fp16
    gemm_kernel<true><<<dim3(T / TILE_N, T / TILE_M, BH), THREADS, SMEM_BYTES>>>(
        QR, QR, S, HD, T, 1.0f / 64.0f);

    // 4) O = S * Vt^T (both K-major), fp32 -> d_out
    gemm_kernel<false><<<dim3(HD / TILE_N, T / TILE_M, BH), THREADS, SMEM_BYTES>>>(
        S, Vt, d_out, T, HD, 1.0f);
}

// round 14
// speedup vs baseline: 1.2361x; 1.2361x over previous
#include <cuda_runtime.h>
#include <cuda_fp16.h>
#include <cstdint>
#include <cstddef>

// ---------------- problem constants ----------------
static constexpr int BH  = 8;     // B*H = 2*4
static constexpr int T   = 2048;  // sequence
static constexpr int HD  = 4096;  // head feature dim N
static constexpr unsigned long long QR_ELEMS = (unsigned long long)BH * T * HD; // 67,108,864
static constexpr unsigned long long S_ELEMS  = (unsigned long long)BH * T * T;  // 33,554,432

// scratch (allocation-free rule: __device__ globals)
__device__ __half g_QR[QR_ELEMS];   // rope(Q), fp16, [bh][t][n]
__device__ __half g_Vt[QR_ELEMS];   // V transposed, fp16, [bh][n][s]
__device__ __half g_S [S_ELEMS];    // scaled scores, fp16, [bh][t][s]

#define DINLINE __device__ __forceinline__

// ---------------- PTX helpers (sm_103 BASE target only — no "a" features) ----
DINLINE uint32_t smem_u32(const void* p) {
    uint32_t a;
    asm("{ .reg .u64 t; cvta.to.shared.u64 t, %1; cvt.u32.u64 %0, t; }" : "=r"(a) : "l"(p));
    return a;
}

#define SWZ128(o) ((o) ^ (((o) >> 3) & 0x70))

DINLINE void cp_async16(uint32_t dst, const void* src) {
    asm volatile("cp.async.cg.shared.global [%0], [%1], 16;" :: "r"(dst), "l"(src) : "memory");
}
#define CP_COMMIT() asm volatile("cp.async.commit_group;" ::: "memory")
#define CP_WAIT(n)  asm volatile("cp.async.wait_group %0;" :: "n"(n) : "memory")

DINLINE void ldsm_x4(uint32_t* r, uint32_t addr) {
    asm volatile("ldmatrix.sync.aligned.m8n8.x4.shared.b16 {%0,%1,%2,%3}, [%4];"
        : "=r"(r[0]), "=r"(r[1]), "=r"(r[2]), "=r"(r[3]) : "r"(addr));
}

DINLINE void mma16816(float* c, const uint32_t* a, const uint32_t* b) {
    asm volatile(
        "mma.sync.aligned.m16n8k16.row.col.f32.f16.f16.f32 "
        "{%0,%1,%2,%3}, {%4,%5,%6,%7}, {%8,%9}, {%0,%1,%2,%3};"
        : "+f"(c[0]), "+f"(c[1]), "+f"(c[2]), "+f"(c[3])
        : "r"(a[0]), "r"(a[1]), "r"(a[2]), "r"(a[3]), "r"(b[0]), "r"(b[1]));
}

// ---------------- prep kernels ----------------

// QR = rope(Q) in fp16. One thread per (even,odd) pair.
__global__ void rope_kernel(const float* __restrict__ Q, __half* __restrict__ qr) {
    long long p = (long long)blockIdx.x * blockDim.x + threadIdx.x; // pair index
    int n2 = (int)(p & (HD / 2 - 1));        // pair index within row
    long long rest = p >> 11;                // / 2048
    int t = (int)(rest & (T - 1));
    float n = (float)(2 * n2);
    // freq = 2^(-n/256) / (2*pi)
    float freq = exp2f(n * (-1.0f / 256.0f)) * 0.15915494309189535f;
    float phase = (float)t * freq;
    float frac = phase - floorf(phase);
    float ph = frac * 6.283185307179586f;
    float s, c;
    sincosf(ph, &s, &c);
    float2 q = ((const float2*)Q)[p];
    __half2 h = __floats2half2_rn(q.x * c - q.y * s, q.y * c + q.x * s);
    ((__half2*)qr)[p] = h;
}

// Vt[bh][n][s] = (half)V[bh][s][n]
__global__ void vtrans_kernel(const float* __restrict__ V, __half* __restrict__ vt) {
    __shared__ __half tile[32][33];
    int bh = blockIdx.z;
    int s0 = blockIdx.x * 32;
    int n0 = blockIdx.y * 32;
    int tx = threadIdx.x, ty = threadIdx.y;
    const float* vsrc = V + (size_t)bh * T * HD;
    #pragma unroll
    for (int j = 0; j < 32; j += 8)
        tile[ty + j][tx] = __float2half(vsrc[(size_t)(s0 + ty + j) * HD + n0 + tx]);
    __syncthreads();
    __half* vdst = vt + (size_t)bh * HD * T;
    #pragma unroll
    for (int j = 0; j < 32; j += 8)
        vdst[(size_t)(n0 + ty + j) * T + s0 + tx] = tile[tx][ty + j];
}

// ---------------- multistage HMMA GEMM core: C[m,n] = sum_k A[m,k]*B[n,k] ----
// A: [*, K] fp16 K-major rows m0..m0+127.  B: [*, K] fp16 K-major rows n0..n0+255.

static constexpr int TILE_M = 128;
static constexpr int TILE_N = 256;
static constexpr int KCH    = 64;               // halves per chunk = 128 B row (SW128 atom)
static constexpr int STAGES = 4;
static constexpr int THREADS = 512;             // 16 warps, 4x4 warp grid
static constexpr int A_STAGE_BYTES = TILE_M * 128;   // 16 KB
static constexpr int B_STAGE_BYTES = TILE_N * 128;   // 32 KB
static constexpr int OFF_A = 0;
static constexpr int OFF_B = STAGES * A_STAGE_BYTES;             // 65536
static constexpr int SMEM_BYTES = OFF_B + STAGES * B_STAGE_BYTES; // 196608 (192 KB)

DINLINE void gemm_mainloop(uint32_t sb, const __half* __restrict__ Abase,
                           const __half* __restrict__ Bbase, int K,
                           int tid, int lane, int warp_m, int warp_n,
                           float acc[2][8][4])
{
    const int NC = K / KCH;

    auto issue_chunk = [&](int kc) {
        int slot = kc & (STAGES - 1);
        const __half* asrc = Abase + kc * KCH;
        uint32_t as = sb + OFF_A + slot * A_STAGE_BYTES;
        #pragma unroll
        for (int j = 0; j < 2; j++) {            // A: 128 rows * 8 chunks / 512 thr
            int i = tid + j * THREADS;
            int r = i >> 3, c8 = i & 7;
            cp_async16(as + SWZ128(r * 128 + c8 * 16), asrc + (size_t)r * K + c8 * 8);
        }
        const __half* bsrc = Bbase + kc * KCH;
        uint32_t bs = sb + OFF_B + slot * B_STAGE_BYTES;
        #pragma unroll
        for (int j = 0; j < 4; j++) {            // B: 256 rows * 8 chunks / 512 thr
            int i = tid + j * THREADS;
            int r = i >> 3, c8 = i & 7;
            cp_async16(bs + SWZ128(r * 128 + c8 * 16), bsrc + (size_t)r * K + c8 * 8);
        }
    };

    // prologue: chunks 0..STAGES-2
    #pragma unroll
    for (int s = 0; s < STAGES - 1; s++) { issue_chunk(s); CP_COMMIT(); }

    #pragma unroll
    for (int mt = 0; mt < 2; mt++)
        #pragma unroll
        for (int nt = 0; nt < 8; nt++)
            #pragma unroll
            for (int j = 0; j < 4; j++) acc[mt][nt][j] = 0.0f;

    // ldmatrix lane geometry
    const int a_row  = warp_m * 32 + (lane & 15);            // + mt*16
    const int a_chk  = lane >> 4;                            // + 2*ks
    const int b_row4 = warp_n * 64 + ((lane >> 4) & 1) * 8 + (lane & 7);  // + nt*8 (nt step 2)
    const int b_chkp = (lane >> 3) & 1;                      // + 2*ks

    for (int kc = 0; kc < NC; kc++) {
        CP_WAIT(STAGES - 2);
        __syncthreads();

        int slot = kc & (STAGES - 1);
        uint32_t as = sb + OFF_A + slot * A_STAGE_BYTES;
        uint32_t bs = sb + OFF_B + slot * B_STAGE_BYTES;

        uint32_t afrag[2][4];
        uint32_t bfrag[8][2];

        // ks = 0 fragment loads first, then refill in their latency shadow
        #pragma unroll
        for (int mt = 0; mt < 2; mt++) {
            int row = a_row + mt * 16;
            int chk = a_chk;
            ldsm_x4(afrag[mt], as + row * 128 + ((chk ^ (row & 7)) << 4));
        }
        #pragma unroll
        for (int nt = 0; nt < 8; nt += 2) {
            int row = b_row4 + nt * 8;
            int chk = b_chkp;
            uint32_t r4[4];
            ldsm_x4(r4, bs + row * 128 + ((chk ^ (row & 7)) << 4));
            bfrag[nt][0] = r4[0]; bfrag[nt][1] = r4[1];
            bfrag[nt + 1][0] = r4[2]; bfrag[nt + 1][1] = r4[3];
        }
        if (kc + STAGES - 1 < NC) issue_chunk(kc + STAGES - 1);
        CP_COMMIT();

        #pragma unroll
        for (int ks = 0; ks < 4; ks++) {
            if (ks > 0) {
                #pragma unroll
                for (int mt = 0; mt < 2; mt++) {
                    int row = a_row + mt * 16;
                    int chk = 2 * ks + a_chk;
                    ldsm_x4(afrag[mt], as + row * 128 + ((chk ^ (row & 7)) << 4));
                }
                #pragma unroll
                for (int nt = 0; nt < 8; nt += 2) {
                    int row = b_row4 + nt * 8;
                    int chk = 2 * ks + b_chkp;
                    uint32_t r4[4];
                    ldsm_x4(r4, bs + row * 128 + ((chk ^ (row & 7)) << 4));
                    bfrag[nt][0] = r4[0]; bfrag[nt][1] = r4[1];
                    bfrag[nt + 1][0] = r4[2]; bfrag[nt + 1][1] = r4[3];
                }
            }
            #pragma unroll
            for (int mt = 0; mt < 2; mt++)
                #pragma unroll
                for (int nt = 0; nt < 8; nt++)
                    mma16816(acc[mt][nt], afrag[mt], bfrag[nt]);
        }
    }
    CP_WAIT(0);
}

// -------- GEMM1 (symmetric): S = (QR * QR^T) / 64, fp16, triangular grid ----
// super-blocks 256x256 over T; blockIdx.x = pair p -> (I,J) with I>=J;
// blockIdx.y = row half h (0/1). Off-diagonal: also mirror-write transposed tile.
__global__ void __launch_bounds__(THREADS, 1)
gemm_sym_kernel(const __half* __restrict__ A, __half* __restrict__ S)
{
    extern __shared__ char smem[];
    uint32_t sb = smem_u32(smem);
    const int tid  = threadIdx.x;
    const int lane = tid & 31;
    const int w    = tid >> 5;
    const int warp_m = w & 3;
    const int warp_n = w >> 2;
    const int bh = blockIdx.z;

    int p = blockIdx.x;
    int I = 0;
    while (((I + 1) * (I + 2)) / 2 <= p) I++;
    int J = p - (I * (I + 1)) / 2;
    const int h  = blockIdx.y;
    const int m0 = I * 256 + h * 128;
    const int n0 = J * 256;

    const __half* Abase = A + ((size_t)bh * T + m0) * HD;
    const __half* Bbase = A + ((size_t)bh * T + n0) * HD;

    float acc[2][8][4];
    gemm_mainloop(sb, Abase, Bbase, HD, tid, lane, warp_m, warp_n, acc);

    const float scale = 1.0f / 64.0f;
    const int group = lane >> 2, tq = lane & 3;

    // normal write: S[m0.., n0..]
    #pragma unroll
    for (int mt = 0; mt < 2; mt++) {
        #pragma unroll
        for (int g2 = 0; g2 < 2; g2++) {
            int row = m0 + warp_m * 32 + mt * 16 + group + g2 * 8;
            __half* outp = S + ((size_t)bh * T + row) * T + n0 + warp_n * 64 + tq * 2;
            #pragma unroll
            for (int nt = 0; nt < 8; nt++) {
                __half2 hh = __floats2half2_rn(acc[mt][nt][g2 * 2 + 0] * scale,
                                               acc[mt][nt][g2 * 2 + 1] * scale);
                *reinterpret_cast<__half2*>(outp + nt * 8) = hh;
            }
        }
    }

    if (I != J) {
        // mirror write: S[n0..n0+256, m0..m0+128] = tile^T, staged through smem
        __syncthreads();                       // everyone done with pipeline smem
        __half* st = reinterpret_cast<__half*>(smem);   // [256][136] halves
        #pragma unroll
        for (int mt = 0; mt < 2; mt++) {
            #pragma unroll
            for (int g2 = 0; g2 < 2; g2++) {
                int r = warp_m * 32 + mt * 16 + group + g2 * 8;   // 0..127
                #pragma unroll
                for (int nt = 0; nt < 8; nt++) {
                    int c = warp_n * 64 + nt * 8 + tq * 2;        // 0..254
                    st[(size_t)c * 136 + r]       = __float2half_rn(acc[mt][nt][g2 * 2 + 0] * scale);
                    st[(size_t)(c + 1) * 136 + r] = __float2half_rn(acc[mt][nt][g2 * 2 + 1] * scale);
                }
            }
        }
        __syncthreads();
        const int rr = tid >> 4;          // 0..31
        const int cc = tid & 15;          // 0..15 (x8 halves)
        __half* Sdst = S + ((size_t)bh * T + n0) * T + m0;
        #pragma unroll
        for (int pass = 0; pass < 8; pass++) {
            int row = pass * 32 + rr;     // 0..255
            uint4 v = *reinterpret_cast<const uint4*>(st + (size_t)row * 136 + cc * 8);
            *reinterpret_cast<uint4*>(Sdst + (size_t)row * T + cc * 8) = v;
        }
    }
}

// -------- GEMM2: O = S * Vt^T (both K-major, K = T), fp32 out ---------------
__global__ void __launch_bounds__(THREADS, 1)
gemm_nn_kernel(const __half* __restrict__ A, const __half* __restrict__ B,
               float* __restrict__ C)
{
    extern __shared__ char smem[];
    uint32_t sb = smem_u32(smem);
    const int tid  = threadIdx.x;
    const int lane = tid & 31;
    const int w    = tid >> 5;
    const int warp_m = w & 3;
    const int warp_n = w >> 2;
    const int bh = blockIdx.z;
    const int m0 = blockIdx.y * TILE_M;
    const int n0 = blockIdx.x * TILE_N;

    const __half* Abase = A + ((size_t)bh * T + m0) * T;    // S rows, K=T
    const __half* Bbase = B + ((size_t)bh * HD + n0) * T;   // Vt rows, K=T

    float acc[2][8][4];
    gemm_mainloop(sb, Abase, Bbase, T, tid, lane, warp_m, warp_n, acc);

    const int group = lane >> 2, tq = lane & 3;
    #pragma unroll
    for (int mt = 0; mt < 2; mt++) {
        #pragma unroll
        for (int g2 = 0; g2 < 2; g2++) {
            int row = m0 + warp_m * 32 + mt * 16 + group + g2 * 8;
            float* outp = C + ((size_t)bh * T + row) * HD + n0 + warp_n * 64 + tq * 2;
            #pragma unroll
            for (int nt = 0; nt < 8; nt++) {
                float2 v = make_float2(acc[mt][nt][g2 * 2 + 0],
                                       acc[mt][nt][g2 * 2 + 1]);
                *reinterpret_cast<float2*>(outp + nt * 8) = v;
            }
        }
    }
}

// ---------------- launch ----------------
extern "C" void kernel_launch(void* const* d_in, const int* in_sizes, int n_in,
                              void* d_out, int out_size)
{
    (void)in_sizes; (void)n_in; (void)out_size;
    const float* Q = (const float*)d_in[0];
    // d_in[1] (K) is unused by the reference computation
    const float* V = (const float*)d_in[2];

    void *qr_p = nullptr, *vt_p = nullptr, *s_p = nullptr;
    cudaGetSymbolAddress(&qr_p, g_QR);
    cudaGetSymbolAddress(&vt_p, g_Vt);
    cudaGetSymbolAddress(&s_p,  g_S);
    __half* QR = (__half*)qr_p;
    __half* Vt = (__half*)vt_p;
    __half* S  = (__half*)s_p;

    cudaFuncSetAttribute((const void*)gemm_sym_kernel,
                         cudaFuncAttributeMaxDynamicSharedMemorySize, SMEM_BYTES);
    cudaFuncSetAttribute((const void*)gemm_nn_kernel,
                         cudaFuncAttributeMaxDynamicSharedMemorySize, SMEM_BYTES);

    // 1) rope(Q) -> QR fp16
    rope_kernel<<<(unsigned)(QR_ELEMS / 2 / 256), 256>>>(Q, QR);

    // 2) V -> Vt fp16 (transpose)
    vtrans_kernel<<<dim3(T / 32, HD / 32, BH), dim3(32, 8)>>>(V, Vt);

    // 3) S = (QR * QR^T) / 64, fp16 — triangular super-block grid (36 pairs x 2 halves)
    gemm_sym_kernel<<<dim3(36, 2, BH), THREADS, SMEM_BYTES>>>(QR, S);

    // 4) O = S * Vt^T (both K-major), fp32 -> d_out
    gemm_nn_kernel<<<dim3(HD / TILE_N, T / TILE_M, BH), THREADS, SMEM_BYTES>>>(
        S, Vt, (float*)d_out);
}